// round 12
// baseline (speedup 1.0000x reference)
#include <cuda_runtime.h>
#include <math.h>

#define BB   64
#define SS   2048
#define DD   1024
#define HH   300
#define OO   2
#define NQ   16                 // d-chunks: 64 floats each
#define QF   16                 // float4s per d-chunk

// Scratch (allocation-free rule: __device__ globals)
__device__ int   g_end[BB];
__device__ int   g_cnt[BB];
__device__ int2  g_rows[BB][SS];     // compacted (s, bitcast mask) per batch
__device__ float g_euph[BB][DD];
__device__ float g_hidden[BB][HH];

// ---------------------------------------------------------------------------
// 1) prep: end-index scan + build compacted valid-row list (s, mask) per b.
//    end = first s with ids[b][s]==1, fallback B (reference's except-path).
//    List order is arbitrary (sum order-insensitive within fp tolerance).
// ---------------------------------------------------------------------------
__global__ __launch_bounds__(1024) void k_prep(const int*   __restrict__ ids,
                                               const float* __restrict__ mask) {
    int b = blockIdx.x;
    int t = threadIdx.x;
    __shared__ int m;
    __shared__ int cnt;
    if (t == 0) { m = 0x7fffffff; cnt = 0; }
    __syncthreads();

    int2   v  = ((const int2*)(ids + b * SS))[t];       // 2 ids per thread
    float2 mk = ((const float2*)(mask + b * SS))[t];    // 2 masks per thread
    if (v.x == 1) atomicMin(&m, 2 * t);
    if (v.y == 1) atomicMin(&m, 2 * t + 1);
    __syncthreads();

    int end = (m == 0x7fffffff) ? BB : m;
    if (t == 0) g_end[b] = end;

    int s0 = 2 * t, s1 = 2 * t + 1;
    if (s0 < end && mk.x != 0.0f) {
        int p = atomicAdd(&cnt, 1);
        g_rows[b][p] = make_int2(s0, __float_as_int(mk.x));
    }
    if (s1 < end && mk.y != 0.0f) {
        int p = atomicAdd(&cnt, 1);
        g_rows[b][p] = make_int2(s1, __float_as_int(mk.y));
    }
    __syncthreads();
    if (t == 0) g_cnt[b] = cnt;
}

// ---------------------------------------------------------------------------
// 2) big masked segment-sum, D-SPLIT: block (b, q) owns d-cols [64q, 64q+64)
//    and streams ALL valid rows of b (uniform work per block of a given b —
//    kills the s-chunk imbalance). Exclusive output ownership -> writes
//    g_euph directly with /end folded in (no partials, no combine, NO
//    atomics). 256 threads: f4 = t&15 (column), ro = t>>4 (row phase).
//    Per warp: 2 rows x 256B contiguous -> fully coalesced.
// ---------------------------------------------------------------------------
__global__ __launch_bounds__(256) void k_reduce(const float* __restrict__ x) {
    int b  = blockIdx.x;
    int q  = blockIdx.y;
    int t  = threadIdx.x;
    int f4 = t & 15;
    int ro = t >> 4;

    __shared__ int2   lst[SS];          // 16 KB
    __shared__ float4 sacc[16][16];     // 4 KB

    cudaGridDependencySynchronize();    // wait for k_prep
    int n = g_cnt[b];
    for (int i = t; i < n; i += 256)
        lst[i] = g_rows[b][i];
    __syncthreads();

    const float4* xp = (const float4*)(x + (long long)b * SS * DD)
                       + q * QF + f4;

    float4 acc = make_float4(0.f, 0.f, 0.f, 0.f);
    int i = ro;
    for (; i + 48 < n; i += 64) {       // 4 rows in flight per thread
        int2 e0 = lst[i];
        int2 e1 = lst[i + 16];
        int2 e2 = lst[i + 32];
        int2 e3 = lst[i + 48];
        float4 v0 = xp[e0.x * (DD / 4)];
        float4 v1 = xp[e1.x * (DD / 4)];
        float4 v2 = xp[e2.x * (DD / 4)];
        float4 v3 = xp[e3.x * (DD / 4)];
        float m0 = __int_as_float(e0.y), m1 = __int_as_float(e1.y);
        float m2 = __int_as_float(e2.y), m3 = __int_as_float(e3.y);
        acc.x += v0.x * m0; acc.y += v0.y * m0; acc.z += v0.z * m0; acc.w += v0.w * m0;
        acc.x += v1.x * m1; acc.y += v1.y * m1; acc.z += v1.z * m1; acc.w += v1.w * m1;
        acc.x += v2.x * m2; acc.y += v2.y * m2; acc.z += v2.z * m2; acc.w += v2.w * m2;
        acc.x += v3.x * m3; acc.y += v3.y * m3; acc.z += v3.z * m3; acc.w += v3.w * m3;
    }
    for (; i < n; i += 16) {
        int2 e = lst[i];
        float m = __int_as_float(e.y);
        float4 v = xp[e.x * (DD / 4)];
        acc.x += v.x * m; acc.y += v.y * m; acc.z += v.z * m; acc.w += v.w * m;
    }

    sacc[ro][f4] = acc;
    __syncthreads();

    // fold 16 row-phases; threads ro==0 own the final 16 float4s
    if (ro == 0) {
        float4 r = sacc[0][f4];
#pragma unroll
        for (int k = 1; k < 16; k++) {
            float4 v = sacc[k][f4];
            r.x += v.x; r.y += v.y; r.z += v.z; r.w += v.w;
        }
        float inv = 1.0f / (float)g_end[b];
        r.x *= inv; r.y *= inv; r.z *= inv; r.w *= inv;
        ((float4*)g_euph[b])[q * QF + f4] = r;
    }
}

// ---------------------------------------------------------------------------
// 3) hidden = tanh(euph @ W1^T + b1).  Grid (32,75)=2400 blocks (measured
//    optimum). PDL: 16KB/block W1 register load before the g_euph sync.
// ---------------------------------------------------------------------------
__global__ __launch_bounds__(128) void k_hidden(const float* __restrict__ W1,
                                                const float* __restrict__ b1) {
    int warp = threadIdx.x >> 5;
    int lane = threadIdx.x & 31;
    int h    = blockIdx.y * 4 + warp;          // 75*4 = 300, always valid
    int b0   = blockIdx.x * 2;                 // 32*2  = 64

    const float4* w4p = (const float4*)(W1 + (long long)h * DD);
    float4 w[8];
#pragma unroll
    for (int i = 0; i < 8; i++) w[i] = w4p[lane + 32 * i];
    float bias = b1[h];

    cudaGridDependencySynchronize();           // wait for g_euph

#pragma unroll
    for (int bi = 0; bi < 2; bi++) {
        const float4* e4 = (const float4*)g_euph[b0 + bi];
        float s = 0.f;
#pragma unroll
        for (int i = 0; i < 8; i++) {
            float4 e = e4[lane + 32 * i];
            s += e.x * w[i].x + e.y * w[i].y + e.z * w[i].z + e.w * w[i].w;
        }
#pragma unroll
        for (int off = 16; off > 0; off >>= 1)
            s += __shfl_xor_sync(0xffffffffu, s, off);
        if (lane == 0)
            g_hidden[b0 + bi][h] = tanhf(s + bias);
    }
}

// ---------------------------------------------------------------------------
// 4) out = hidden @ W2^T + b2.  Warp per (b, o): 128 warps over 8 blocks.
//    PDL: W2 slice loaded pre-sync.
// ---------------------------------------------------------------------------
__global__ __launch_bounds__(512) void k_out(const float* __restrict__ W2,
                                             const float* __restrict__ b2,
                                             float* __restrict__ out) {
    int gw   = blockIdx.x * 16 + (threadIdx.x >> 5);   // 0..127
    int lane = threadIdx.x & 31;
    int b    = gw >> 1;
    int o    = gw & 1;

    const float* w = W2 + o * HH;
    float wr[10];                              // ceil(300/32)=10 per lane
#pragma unroll
    for (int i = 0; i < 10; i++) {
        int k = lane + 32 * i;
        wr[i] = (k < HH) ? w[k] : 0.0f;
    }
    float bias = b2[o];

    cudaGridDependencySynchronize();           // wait for g_hidden

    const float* hid = g_hidden[b];
    float s = 0.f;
#pragma unroll
    for (int i = 0; i < 10; i++) {
        int k = lane + 32 * i;
        if (k < HH) s += hid[k] * wr[i];
    }
#pragma unroll
    for (int off = 16; off > 0; off >>= 1)
        s += __shfl_xor_sync(0xffffffffu, s, off);
    if (lane == 0)
        out[b * OO + o] = s + bias;
}

// ---------------------------------------------------------------------------
template <typename... Args>
static inline void launch_pdl(void (*kern)(Args...), dim3 grid, dim3 block,
                              Args... args) {
    cudaLaunchConfig_t cfg = {};
    cfg.gridDim  = grid;
    cfg.blockDim = block;
    cudaLaunchAttribute attr[1];
    attr[0].id = cudaLaunchAttributeProgrammaticStreamSerialization;
    attr[0].val.programmaticStreamSerializationAllowed = 1;
    cfg.attrs    = attr;
    cfg.numAttrs = 1;
    cudaLaunchKernelEx(&cfg, kern, args...);
}

extern "C" void kernel_launch(void* const* d_in, const int* in_sizes, int n_in,
                              void* d_out, int out_size) {
    const float* x    = (const float*)d_in[0];       // [B,S,D] f32
    const int*   ids  = (const int*)d_in[1];         // [B,S]   i32 (JAX x64 off)
    const float* mask = (const float*)d_in[2];       // [B,S,1] f32
    const float* W1   = (const float*)d_in[3];       // [H,D]
    const float* b1   = (const float*)d_in[4];       // [H]
    const float* W2   = (const float*)d_in[5];       // [OUT,H]
    const float* b2   = (const float*)d_in[6];       // [OUT]
    float*       out  = (float*)d_out;               // [B,OUT]

    k_prep<<<BB, 1024>>>(ids, mask);
    launch_pdl(k_reduce, dim3(BB, NQ), dim3(256), x);
    launch_pdl(k_hidden, dim3(32, HH / 4), dim3(128), W1, b1);
    launch_pdl(k_out,    dim3(8), dim3(512), W2, b2, out);
}

// round 13
// speedup vs baseline: 1.1853x; 1.1853x over previous
#include <cuda_runtime.h>
#include <math.h>

#define BB   64
#define SS   2048
#define DD   1024
#define HH   300
#define OO   2
#define SCH  16                 // s-chunks for the big reduction
#define SPC  (SS / SCH)         // 128 s per chunk
#define D4   (DD / 4)           // 256 float4 per row

// Scratch (allocation-free rule: __device__ globals)
__device__ int   g_end[BB];
__device__ float g_partial[BB][SCH][DD];
__device__ float g_euph[BB][DD];
__device__ float g_hidden[BB][HH];

// ---------------------------------------------------------------------------
// 1) end-index scan. end = first s with ids[b][s]==1, fallback B (reference's
//    except-path quirk). Early trigger: k_reduce's mask preamble overlaps us.
// ---------------------------------------------------------------------------
__global__ __launch_bounds__(1024) void k_end(const int* __restrict__ ids) {
    cudaTriggerProgrammaticLaunchCompletion();
    int b = blockIdx.x;
    int t = threadIdx.x;
    __shared__ int m;
    if (t == 0) m = 0x7fffffff;
    __syncthreads();
    const int2* row = (const int2*)(ids + b * SS);
    int2 v = row[t];                       // 1024 threads * 2 ids = 2048
    if (v.x == 1) atomicMin(&m, 2 * t);
    if (v.y == 1) atomicMin(&m, 2 * t + 1);
    __syncthreads();
    if (t == 0) g_end[b] = (m == 0x7fffffff) ? BB : m;
}

// ---------------------------------------------------------------------------
// 2) big masked segment-sum, s-chunk split, COMPACTED row list (~DRAM cap;
//    R12 proved d-split fragments the stream — keep contiguous 16KB bursts).
//    Early trigger lets k_hidden prefetch its L2-resident W1 during our
//    mainloop (L2 has headroom over the DRAM-bound stream).
// ---------------------------------------------------------------------------
__global__ __launch_bounds__(256) void k_reduce(const float* __restrict__ x,
                                                const float* __restrict__ mask) {
    cudaTriggerProgrammaticLaunchCompletion();
    int b = blockIdx.x;
    int c = blockIdx.y;
    int t = threadIdx.x;
    int s0 = c * SPC;

    // independent preamble: raw mask load (does not need g_end)
    float mraw = 0.0f;
    if (t < SPC) mraw = mask[b * SS + s0 + t];

    cudaGridDependencySynchronize();       // wait for k_end's g_end
    int end = g_end[b];

    __shared__ float s_m[SPC];
    __shared__ int   s_idx[SPC];
    __shared__ int   s_cnt;
    if (t == 0) s_cnt = 0;
    __syncthreads();

    if (t < SPC && (s0 + t) < end && mraw != 0.0f) {
        int p = atomicAdd(&s_cnt, 1);
        s_idx[p] = t;
        s_m[p]   = mraw;
    }
    __syncthreads();
    int n = s_cnt;

    const float4* xp = (const float4*)(x + (long long)b * SS * DD)
                       + (long long)s0 * D4 + t;

    float4 acc = make_float4(0.f, 0.f, 0.f, 0.f);
    int i = 0;
    for (; i + 4 <= n; i += 4) {
        int   j0 = s_idx[i],     j1 = s_idx[i + 1];
        int   j2 = s_idx[i + 2], j3 = s_idx[i + 3];
        float m0 = s_m[i],       m1 = s_m[i + 1];
        float m2 = s_m[i + 2],   m3 = s_m[i + 3];
        float4 v0 = xp[j0 * D4];
        float4 v1 = xp[j1 * D4];
        float4 v2 = xp[j2 * D4];
        float4 v3 = xp[j3 * D4];
        acc.x += v0.x * m0; acc.y += v0.y * m0; acc.z += v0.z * m0; acc.w += v0.w * m0;
        acc.x += v1.x * m1; acc.y += v1.y * m1; acc.z += v1.z * m1; acc.w += v1.w * m1;
        acc.x += v2.x * m2; acc.y += v2.y * m2; acc.z += v2.z * m2; acc.w += v2.w * m2;
        acc.x += v3.x * m3; acc.y += v3.y * m3; acc.z += v3.z * m3; acc.w += v3.w * m3;
    }
    for (; i < n; i++) {
        int   j = s_idx[i];
        float m = s_m[i];
        float4 v = xp[j * D4];
        acc.x += v.x * m; acc.y += v.y * m; acc.z += v.z * m; acc.w += v.w * m;
    }
    ((float4*)g_partial[b][c])[t] = acc;
}

// ---------------------------------------------------------------------------
// 3) fold the SCH partials and divide by end. Grid (64 b, 4 q) = 256 blocks.
// ---------------------------------------------------------------------------
__global__ __launch_bounds__(256) void k_combine() {
    cudaTriggerProgrammaticLaunchCompletion();
    int b = blockIdx.x;
    int d = blockIdx.y * 256 + threadIdx.x;
    cudaGridDependencySynchronize();
    float inv = 1.0f / (float)g_end[b];
    float acc = 0.f;
#pragma unroll
    for (int c = 0; c < SCH; c++)
        acc += g_partial[b][c][d];
    g_euph[b][d] = acc * inv;
}

// ---------------------------------------------------------------------------
// 4) hidden = tanh(euph @ W1^T + b1).  Grid (32,75)=2400 blocks (measured
//    optimum). W1 register prefetch runs pre-sync — with the early trigger
//    chain it overlaps the reduce mainloop (W1 is L2-resident: 1.2MB unique).
// ---------------------------------------------------------------------------
__global__ __launch_bounds__(128) void k_hidden(const float* __restrict__ W1,
                                                const float* __restrict__ b1) {
    cudaTriggerProgrammaticLaunchCompletion();
    int warp = threadIdx.x >> 5;
    int lane = threadIdx.x & 31;
    int h    = blockIdx.y * 4 + warp;          // 75*4 = 300, always valid
    int b0   = blockIdx.x * 2;                 // 32*2  = 64

    // independent preamble: W1 row + bias (inputs, not produced upstream)
    const float4* w4p = (const float4*)(W1 + (long long)h * DD);
    float4 w[8];
#pragma unroll
    for (int i = 0; i < 8; i++) w[i] = w4p[lane + 32 * i];
    float bias = b1[h];

    cudaGridDependencySynchronize();           // wait for g_euph

#pragma unroll
    for (int bi = 0; bi < 2; bi++) {
        const float4* e4 = (const float4*)g_euph[b0 + bi];
        float s = 0.f;
#pragma unroll
        for (int i = 0; i < 8; i++) {
            float4 e = e4[lane + 32 * i];
            s += e.x * w[i].x + e.y * w[i].y + e.z * w[i].z + e.w * w[i].w;
        }
#pragma unroll
        for (int off = 16; off > 0; off >>= 1)
            s += __shfl_xor_sync(0xffffffffu, s, off);
        if (lane == 0)
            g_hidden[b0 + bi][h] = tanhf(s + bias);
    }
}

// ---------------------------------------------------------------------------
// 5) out = hidden @ W2^T + b2.  Warp per (b, o): 128 warps over 8 blocks.
//    W2 slice prefetched pre-sync (overlaps k_hidden via its early trigger).
// ---------------------------------------------------------------------------
__global__ __launch_bounds__(512) void k_out(const float* __restrict__ W2,
                                             const float* __restrict__ b2,
                                             float* __restrict__ out) {
    int gw   = blockIdx.x * 16 + (threadIdx.x >> 5);   // 0..127
    int lane = threadIdx.x & 31;
    int b    = gw >> 1;
    int o    = gw & 1;

    const float* w = W2 + o * HH;
    float wr[10];                              // ceil(300/32)=10 per lane
#pragma unroll
    for (int i = 0; i < 10; i++) {
        int k = lane + 32 * i;
        wr[i] = (k < HH) ? w[k] : 0.0f;
    }
    float bias = b2[o];

    cudaGridDependencySynchronize();           // wait for g_hidden

    const float* hid = g_hidden[b];
    float s = 0.f;
#pragma unroll
    for (int i = 0; i < 10; i++) {
        int k = lane + 32 * i;
        if (k < HH) s += hid[k] * wr[i];
    }
#pragma unroll
    for (int off = 16; off > 0; off >>= 1)
        s += __shfl_xor_sync(0xffffffffu, s, off);
    if (lane == 0)
        out[b * OO + o] = s + bias;
}

// ---------------------------------------------------------------------------
template <typename... Args>
static inline void launch_pdl(void (*kern)(Args...), dim3 grid, dim3 block,
                              Args... args) {
    cudaLaunchConfig_t cfg = {};
    cfg.gridDim  = grid;
    cfg.blockDim = block;
    cudaLaunchAttribute attr[1];
    attr[0].id = cudaLaunchAttributeProgrammaticStreamSerialization;
    attr[0].val.programmaticStreamSerializationAllowed = 1;
    cfg.attrs    = attr;
    cfg.numAttrs = 1;
    cudaLaunchKernelEx(&cfg, kern, args...);
}

extern "C" void kernel_launch(void* const* d_in, const int* in_sizes, int n_in,
                              void* d_out, int out_size) {
    const float* x    = (const float*)d_in[0];       // [B,S,D] f32
    const int*   ids  = (const int*)d_in[1];         // [B,S]   i32 (JAX x64 off)
    const float* mask = (const float*)d_in[2];       // [B,S,1] f32
    const float* W1   = (const float*)d_in[3];       // [H,D]
    const float* b1   = (const float*)d_in[4];       // [H]
    const float* W2   = (const float*)d_in[5];       // [OUT,H]
    const float* b2   = (const float*)d_in[6];       // [OUT]
    float*       out  = (float*)d_out;               // [B,OUT]

    k_end<<<BB, 1024>>>(ids);
    launch_pdl(k_reduce,  dim3(BB, SCH), dim3(256), x, mask);
    launch_pdl(k_combine, dim3(BB, 4),   dim3(256));
    launch_pdl(k_hidden,  dim3(32, HH / 4), dim3(128), W1, b1);
    launch_pdl(k_out,     dim3(8), dim3(512), W2, b2, out);
}